// round 6
// baseline (speedup 1.0000x reference)
#include <cuda_runtime.h>
#include <cstdint>

// N_NODES=50000, N_EDGES=800000, IN=128, HID=128, OUT=64. int32 edge indices.
#define NMAX 50048
#define EMAX 800000
#define IN_DIM 128
#define HID_DIM 128
#define OUT_DIM 64

__device__ int   g_degi[NMAX];
__device__ int   g_rowptr[NMAX + 1];
__device__ int   g_cursor[NMAX];
__device__ int   g_csr_src[EMAX];
__device__ float g_dinv[NMAX];
__device__ float g_h1[NMAX * HID_DIM];
__device__ float g_acc1[NMAX * HID_DIM];
__device__ float g_h2[NMAX * OUT_DIM];

typedef unsigned long long ull;

__device__ __forceinline__ ull pack2(float x, float y) {
    ull r;
    asm("mov.b64 %0, {%1, %2};" : "=l"(r) : "f"(x), "f"(y));
    return r;
}
__device__ __forceinline__ void unpack2(ull v, float& x, float& y) {
    asm("mov.b64 {%0, %1}, %2;" : "=f"(x), "=f"(y) : "l"(v));
}
__device__ __forceinline__ void fma2(ull& d, ull a, ull b) {
    asm("fma.rn.f32x2 %0, %1, %2, %0;" : "+l"(d) : "l"(a), "l"(b));
}

// ---------------------------------------------------------------------------
__global__ void deg_kernel(const int* __restrict__ dst, int* __restrict__ degi, int E) {
    int i = blockIdx.x * blockDim.x + threadIdx.x;
    if (i < E) atomicAdd(&degi[dst[i]], 1);
}

__global__ void scan_kernel(const int* __restrict__ degi, int* __restrict__ rowptr,
                            int* __restrict__ cursor, float* __restrict__ dinv,
                            int N, int E) {
    __shared__ int warp_sums[32];
    int t = threadIdx.x;                    // 1024 threads
    int CH = (N + 1023) >> 10;
    int lo = t * CH, hi = min(lo + CH, N);
    int sum = 0;
    for (int i = lo; i < hi; i++) sum += degi[i];

    int lane = t & 31, wid = t >> 5;
    int v = sum;
#pragma unroll
    for (int o = 1; o < 32; o <<= 1) {
        int u = __shfl_up_sync(~0u, v, o);
        if (lane >= o) v += u;
    }
    if (lane == 31) warp_sums[wid] = v;
    __syncthreads();
    if (wid == 0) {
        int w = warp_sums[lane];
#pragma unroll
        for (int o = 1; o < 32; o <<= 1) {
            int u = __shfl_up_sync(~0u, w, o);
            if (lane >= o) w += u;
        }
        warp_sums[lane] = w;
    }
    __syncthreads();
    int run = v - sum + (wid > 0 ? warp_sums[wid - 1] : 0);
    for (int i = lo; i < hi; i++) {
        int d = degi[i];
        rowptr[i] = run;
        cursor[i] = run;
        dinv[i] = d > 0 ? rsqrtf((float)d) : 0.0f;
        run += d;
    }
    if (t == 0) rowptr[N] = E;
}

__global__ void fill_kernel(const int* __restrict__ src, const int* __restrict__ dst,
                            int* __restrict__ cursor, int* __restrict__ csr_src, int E) {
    int e = blockIdx.x * blockDim.x + threadIdx.x;
    if (e < E) {
        int pos = atomicAdd(&cursor[dst[e]], 1);
        csr_src[pos] = src[e];
    }
}

// ---------------------------------------------------------------------------
// GEMM: Y = act(X) @ W, Y[row] *= scale[row]. W-only smem (64/32 KB -> 3 CTA/SM).
// X read via warp-converged LDG.128 (1-wavefront broadcast). Packed f32x2 FMA.
template <int K, int N, bool RELU>
__global__ void __launch_bounds__(256, 3)
gemm_kernel(const float* __restrict__ X, const float* __restrict__ W,
            const float* __restrict__ scale, float* __restrict__ Y, int M) {
    constexpr int CPT = N / 32;
    extern __shared__ float Ws[];   // K*N

    int t = threadIdx.x;
    for (int i = t; i < K * N / 4; i += 256)
        ((float4*)Ws)[i] = ((const float4*)W)[i];
    __syncthreads();

    int tx = t & 31;
    int ty = t >> 5;
    int row0 = blockIdx.x * 64 + ty * 8;

    // clamped row pointers (reads safe; stores guarded)
    const float4* xr[8];
#pragma unroll
    for (int r = 0; r < 8; r++) {
        int gr = min(row0 + r, M - 1);
        xr[r] = (const float4*)(X + (size_t)gr * K);
    }

    if constexpr (CPT == 4) {
        ull accxy[8], acczw[8];
#pragma unroll
        for (int r = 0; r < 8; r++) { accxy[r] = 0ull; acczw[r] = 0ull; }
#pragma unroll 2
        for (int k = 0; k < K; k += 4) {
            ull bxy[4], bzw[4];
#pragma unroll
            for (int j = 0; j < 4; j++) {
                longlong2 bb = *(const longlong2*)&Ws[(k + j) * N + tx * 4];
                bxy[j] = (ull)bb.x; bzw[j] = (ull)bb.y;
            }
#pragma unroll
            for (int r = 0; r < 8; r++) {
                float4 av = xr[r][k >> 2];
                if (RELU) {
                    av.x = fmaxf(av.x, 0.f); av.y = fmaxf(av.y, 0.f);
                    av.z = fmaxf(av.z, 0.f); av.w = fmaxf(av.w, 0.f);
                }
                ull a0 = pack2(av.x, av.x), a1 = pack2(av.y, av.y);
                ull a2 = pack2(av.z, av.z), a3 = pack2(av.w, av.w);
                fma2(accxy[r], a0, bxy[0]); fma2(acczw[r], a0, bzw[0]);
                fma2(accxy[r], a1, bxy[1]); fma2(acczw[r], a1, bzw[1]);
                fma2(accxy[r], a2, bxy[2]); fma2(acczw[r], a2, bzw[2]);
                fma2(accxy[r], a3, bxy[3]); fma2(acczw[r], a3, bzw[3]);
            }
        }
#pragma unroll
        for (int r = 0; r < 8; r++) {
            int gr = row0 + r;
            if (gr < M) {
                float s = scale[gr];
                float4 o;
                unpack2(accxy[r], o.x, o.y);
                unpack2(acczw[r], o.z, o.w);
                o.x *= s; o.y *= s; o.z *= s; o.w *= s;
                *(float4*)&Y[(size_t)gr * N + tx * 4] = o;
            }
        }
    } else {
        ull acc[8];
#pragma unroll
        for (int r = 0; r < 8; r++) acc[r] = 0ull;
#pragma unroll 2
        for (int k = 0; k < K; k += 4) {
            ull bk[4];
#pragma unroll
            for (int j = 0; j < 4; j++)
                bk[j] = *(const ull*)&Ws[(k + j) * N + tx * 2];
#pragma unroll
            for (int r = 0; r < 8; r++) {
                float4 av = xr[r][k >> 2];
                if (RELU) {
                    av.x = fmaxf(av.x, 0.f); av.y = fmaxf(av.y, 0.f);
                    av.z = fmaxf(av.z, 0.f); av.w = fmaxf(av.w, 0.f);
                }
                fma2(acc[r], pack2(av.x, av.x), bk[0]);
                fma2(acc[r], pack2(av.y, av.y), bk[1]);
                fma2(acc[r], pack2(av.z, av.z), bk[2]);
                fma2(acc[r], pack2(av.w, av.w), bk[3]);
            }
        }
#pragma unroll
        for (int r = 0; r < 8; r++) {
            int gr = row0 + r;
            if (gr < M) {
                float s = scale[gr];
                float2 o;
                unpack2(acc[r], o.x, o.y);
                o.x *= s; o.y *= s;
                *(float2*)&Y[(size_t)gr * N + tx * 2] = o;
            }
        }
    }
}

// ---------------------------------------------------------------------------
// Agg C=128: warp per node, lane owns float4. Batch-16: one coalesced index
// load (lanes 0-15 pattern) + shfl distribution; gathers in two MLP-8 groups.
__global__ void agg128_kernel(const int* __restrict__ rowptr, const int* __restrict__ csr_src,
                              const float* __restrict__ h, const float* __restrict__ dinv,
                              const float* __restrict__ bias, float* __restrict__ out, int N) {
    int warp = (blockIdx.x * blockDim.x + threadIdx.x) >> 5;
    int lane = threadIdx.x & 31;
    if (warp >= N) return;
    int j = rowptr[warp], end = rowptr[warp + 1];
    const float4* hv = (const float4*)h;
    float4 acc = make_float4(0.f, 0.f, 0.f, 0.f);

    while (j + 16 <= end) {
        int idx = csr_src[j + (lane & 15)];
        float4 v[8];
#pragma unroll
        for (int u = 0; u < 8; u++) {
            int s = __shfl_sync(~0u, idx, u);
            v[u] = hv[(size_t)s * 32 + lane];
        }
#pragma unroll
        for (int u = 0; u < 8; u++) {
            acc.x += v[u].x; acc.y += v[u].y; acc.z += v[u].z; acc.w += v[u].w;
        }
#pragma unroll
        for (int u = 8; u < 16; u++) {
            int s = __shfl_sync(~0u, idx, u);
            v[u - 8] = hv[(size_t)s * 32 + lane];
        }
#pragma unroll
        for (int u = 0; u < 8; u++) {
            acc.x += v[u].x; acc.y += v[u].y; acc.z += v[u].z; acc.w += v[u].w;
        }
        j += 16;
    }
    int rem = end - j;
    if (rem > 0) {
        int idx = csr_src[j + min(lane & 15, rem - 1)];
#pragma unroll
        for (int u = 0; u < 16; u++) {
            if (u < rem) {
                int s = __shfl_sync(~0u, idx, u);
                float4 a = hv[(size_t)s * 32 + lane];
                acc.x += a.x; acc.y += a.y; acc.z += a.z; acc.w += a.w;
            }
        }
    }
    float dn = dinv[warp];
    float4 bv = ((const float4*)bias)[lane];
    float4 o = make_float4(acc.x * dn + bv.x, acc.y * dn + bv.y,
                           acc.z * dn + bv.z, acc.w * dn + bv.w);
    ((float4*)out)[(size_t)warp * 32 + lane] = o;
}

// Agg C=64: warp per node, lane owns float2. Batch-16 with full MLP-16.
__global__ void agg64_kernel(const int* __restrict__ rowptr, const int* __restrict__ csr_src,
                             const float* __restrict__ h, const float* __restrict__ dinv,
                             const float* __restrict__ bias, float* __restrict__ out, int N) {
    int warp = (blockIdx.x * blockDim.x + threadIdx.x) >> 5;
    int lane = threadIdx.x & 31;
    if (warp >= N) return;
    int j = rowptr[warp], end = rowptr[warp + 1];
    const float2* hv = (const float2*)h;
    float2 acc = make_float2(0.f, 0.f);

    while (j + 16 <= end) {
        int idx = csr_src[j + (lane & 15)];
        float2 v[16];
#pragma unroll
        for (int u = 0; u < 16; u++) {
            int s = __shfl_sync(~0u, idx, u);
            v[u] = hv[(size_t)s * 32 + lane];
        }
#pragma unroll
        for (int u = 0; u < 16; u++) { acc.x += v[u].x; acc.y += v[u].y; }
        j += 16;
    }
    int rem = end - j;
    if (rem > 0) {
        int idx = csr_src[j + min(lane & 15, rem - 1)];
#pragma unroll
        for (int u = 0; u < 16; u++) {
            if (u < rem) {
                int s = __shfl_sync(~0u, idx, u);
                float2 a = hv[(size_t)s * 32 + lane];
                acc.x += a.x; acc.y += a.y;
            }
        }
    }
    float dn = dinv[warp];
    float2 bv = ((const float2*)bias)[lane];
    float2 o = make_float2(acc.x * dn + bv.x, acc.y * dn + bv.y);
    ((float2*)out)[(size_t)warp * 32 + lane] = o;
}

// ---------------------------------------------------------------------------
extern "C" void kernel_launch(void* const* d_in, const int* in_sizes, int n_in,
                              void* d_out, int out_size) {
    const float* x  = (const float*)d_in[0];
    const int*   ei = (const int*)d_in[1];
    const float* W1 = (const float*)d_in[2];
    const float* b1 = (const float*)d_in[3];
    const float* W2 = (const float*)d_in[4];
    const float* b2 = (const float*)d_in[5];
    float* out = (float*)d_out;

    const int N = in_sizes[0] / IN_DIM;
    const int E = in_sizes[1] / 2;
    const int* src = ei;
    const int* dst = ei + E;

    int *p_degi, *p_rowptr, *p_cursor, *p_csr;
    float *p_dinv, *p_h1, *p_acc1, *p_h2;
    cudaGetSymbolAddress((void**)&p_degi,   g_degi);
    cudaGetSymbolAddress((void**)&p_rowptr, g_rowptr);
    cudaGetSymbolAddress((void**)&p_cursor, g_cursor);
    cudaGetSymbolAddress((void**)&p_csr,    g_csr_src);
    cudaGetSymbolAddress((void**)&p_dinv,   g_dinv);
    cudaGetSymbolAddress((void**)&p_h1,     g_h1);
    cudaGetSymbolAddress((void**)&p_acc1,   g_acc1);
    cudaGetSymbolAddress((void**)&p_h2,     g_h2);

    const int smem1 = IN_DIM * HID_DIM * 4;   // 64 KB
    const int smem2 = HID_DIM * OUT_DIM * 4;  // 32 KB
    cudaFuncSetAttribute((const void*)gemm_kernel<IN_DIM, HID_DIM, false>,
                         cudaFuncAttributeMaxDynamicSharedMemorySize, smem1);
    cudaFuncSetAttribute((const void*)gemm_kernel<HID_DIM, OUT_DIM, true>,
                         cudaFuncAttributeMaxDynamicSharedMemorySize, smem2);

    // --- CSR build ---
    cudaMemsetAsync(p_degi, 0, (size_t)N * sizeof(int));
    deg_kernel<<<(E + 255) / 256, 256>>>(dst, p_degi, E);
    scan_kernel<<<1, 1024>>>(p_degi, p_rowptr, p_cursor, p_dinv, N, E);
    fill_kernel<<<(E + 255) / 256, 256>>>(src, dst, p_cursor, p_csr, E);

    // --- layer 1 ---
    gemm_kernel<IN_DIM, HID_DIM, false>
        <<<(N + 63) / 64, 256, smem1>>>(x, W1, p_dinv, p_h1, N);
    agg128_kernel<<<(N * 32 + 255) / 256, 256>>>(p_rowptr, p_csr, p_h1, p_dinv, b1, p_acc1, N);

    // --- layer 2 ---
    gemm_kernel<HID_DIM, OUT_DIM, true>
        <<<(N + 63) / 64, 256, smem2>>>(p_acc1, W2, p_dinv, p_h2, N);
    agg64_kernel<<<(N * 32 + 255) / 256, 256>>>(p_rowptr, p_csr, p_h2, p_dinv, b2, out, N);
}

// round 7
// speedup vs baseline: 1.2120x; 1.2120x over previous
#include <cuda_runtime.h>
#include <cstdint>

// N_NODES=50000, N_EDGES=800000, IN=128, HID=128, OUT=64. int32 edge indices.
#define NMAX 50048
#define EMAX 800000
#define IN_DIM 128
#define HID_DIM 128
#define OUT_DIM 64

__device__ int   g_degi[NMAX];
__device__ int   g_rowptr[NMAX + 1];
__device__ int   g_cursor[NMAX];
__device__ int   g_csr_src[EMAX];
__device__ float g_dinv[NMAX];
__device__ float g_h1[NMAX * HID_DIM];
__device__ float g_acc1[NMAX * HID_DIM];
__device__ float g_h2[NMAX * OUT_DIM];

typedef unsigned long long ull;

__device__ __forceinline__ ull pack2(float x, float y) {
    ull r;
    asm("mov.b64 %0, {%1, %2};" : "=l"(r) : "f"(x), "f"(y));
    return r;
}
__device__ __forceinline__ void unpack2(ull v, float& x, float& y) {
    asm("mov.b64 {%0, %1}, %2;" : "=f"(x), "=f"(y) : "l"(v));
}
__device__ __forceinline__ void fma2(ull& d, ull a, ull b) {
    asm("fma.rn.f32x2 %0, %1, %2, %0;" : "+l"(d) : "l"(a), "l"(b));
}

// ---------------------------------------------------------------------------
__global__ void deg_kernel(const int* __restrict__ dst, int* __restrict__ degi, int E) {
    int i = blockIdx.x * blockDim.x + threadIdx.x;
    if (i < E) atomicAdd(&degi[dst[i]], 1);
}

__global__ void scan_kernel(const int* __restrict__ degi, int* __restrict__ rowptr,
                            int* __restrict__ cursor, float* __restrict__ dinv,
                            int N, int E) {
    __shared__ int warp_sums[32];
    int t = threadIdx.x;                    // 1024 threads
    int CH = (N + 1023) >> 10;
    int lo = t * CH, hi = min(lo + CH, N);
    int sum = 0;
    for (int i = lo; i < hi; i++) sum += degi[i];

    int lane = t & 31, wid = t >> 5;
    int v = sum;
#pragma unroll
    for (int o = 1; o < 32; o <<= 1) {
        int u = __shfl_up_sync(~0u, v, o);
        if (lane >= o) v += u;
    }
    if (lane == 31) warp_sums[wid] = v;
    __syncthreads();
    if (wid == 0) {
        int w = warp_sums[lane];
#pragma unroll
        for (int o = 1; o < 32; o <<= 1) {
            int u = __shfl_up_sync(~0u, w, o);
            if (lane >= o) w += u;
        }
        warp_sums[lane] = w;
    }
    __syncthreads();
    int run = v - sum + (wid > 0 ? warp_sums[wid - 1] : 0);
    for (int i = lo; i < hi; i++) {
        int d = degi[i];
        rowptr[i] = run;
        cursor[i] = run;
        dinv[i] = d > 0 ? rsqrtf((float)d) : 0.0f;
        run += d;
    }
    if (t == 0) rowptr[N] = E;
}

__global__ void fill_kernel(const int* __restrict__ src, const int* __restrict__ dst,
                            int* __restrict__ cursor, int* __restrict__ csr_src, int E) {
    int e = blockIdx.x * blockDim.x + threadIdx.x;
    if (e < E) {
        int pos = atomicAdd(&cursor[dst[e]], 1);
        csr_src[pos] = src[e];
    }
}

// ---------------------------------------------------------------------------
// Tiled fp32 GEMM with packed f32x2 FMA (R5 version — known 58/25 us).
template <int K, int N, bool RELU>
__global__ void gemm_kernel(const float* __restrict__ X, const float* __restrict__ W,
                            const float* __restrict__ scale,
                            float* __restrict__ Y, int M) {
    constexpr int ROWS = 64;
    constexpr int CPT = N / 32;
    extern __shared__ float smem[];
    float* Ws = smem;              // K*N
    float* Xs = smem + K * N;      // ROWS*K

    int t = threadIdx.x;
    for (int i = t; i < K * N / 4; i += 256)
        ((float4*)Ws)[i] = ((const float4*)W)[i];

    int row0 = blockIdx.x * ROWS;
    constexpr int K4 = K / 4;
    for (int i = t; i < ROWS * K4; i += 256) {
        int gr = row0 + i / K4;
        float4 v = make_float4(0.f, 0.f, 0.f, 0.f);
        if (gr < M) v = ((const float4*)X)[(size_t)gr * K4 + (i % K4)];
        if (RELU) {
            v.x = fmaxf(v.x, 0.f); v.y = fmaxf(v.y, 0.f);
            v.z = fmaxf(v.z, 0.f); v.w = fmaxf(v.w, 0.f);
        }
        ((float4*)Xs)[i] = v;
    }
    __syncthreads();

    int tx = t & 31;
    int ty = t >> 5;

    if constexpr (CPT == 4) {
        ull accxy[8], acczw[8];
#pragma unroll
        for (int r = 0; r < 8; r++) { accxy[r] = 0ull; acczw[r] = 0ull; }
#pragma unroll 2
        for (int k = 0; k < K; k += 4) {
            ull bxy[4], bzw[4];
#pragma unroll
            for (int j = 0; j < 4; j++) {
                longlong2 bb = *(const longlong2*)&Ws[(k + j) * N + tx * 4];
                bxy[j] = (ull)bb.x; bzw[j] = (ull)bb.y;
            }
#pragma unroll
            for (int r = 0; r < 8; r++) {
                float4 av = *(const float4*)&Xs[(ty * 8 + r) * K + k];
                ull a0 = pack2(av.x, av.x), a1 = pack2(av.y, av.y);
                ull a2 = pack2(av.z, av.z), a3 = pack2(av.w, av.w);
                fma2(accxy[r], a0, bxy[0]); fma2(acczw[r], a0, bzw[0]);
                fma2(accxy[r], a1, bxy[1]); fma2(acczw[r], a1, bzw[1]);
                fma2(accxy[r], a2, bxy[2]); fma2(acczw[r], a2, bzw[2]);
                fma2(accxy[r], a3, bxy[3]); fma2(acczw[r], a3, bzw[3]);
            }
        }
#pragma unroll
        for (int r = 0; r < 8; r++) {
            int gr = row0 + ty * 8 + r;
            if (gr < M) {
                float s = scale[gr];
                float4 o;
                unpack2(accxy[r], o.x, o.y);
                unpack2(acczw[r], o.z, o.w);
                o.x *= s; o.y *= s; o.z *= s; o.w *= s;
                *(float4*)&Y[(size_t)gr * N + tx * 4] = o;
            }
        }
    } else {
        ull acc[8];
#pragma unroll
        for (int r = 0; r < 8; r++) acc[r] = 0ull;
#pragma unroll 2
        for (int k = 0; k < K; k += 4) {
            ull bk[4];
#pragma unroll
            for (int j = 0; j < 4; j++)
                bk[j] = *(const ull*)&Ws[(k + j) * N + tx * 2];
#pragma unroll
            for (int r = 0; r < 8; r++) {
                float4 av = *(const float4*)&Xs[(ty * 8 + r) * K + k];
                fma2(acc[r], pack2(av.x, av.x), bk[0]);
                fma2(acc[r], pack2(av.y, av.y), bk[1]);
                fma2(acc[r], pack2(av.z, av.z), bk[2]);
                fma2(acc[r], pack2(av.w, av.w), bk[3]);
            }
        }
#pragma unroll
        for (int r = 0; r < 8; r++) {
            int gr = row0 + ty * 8 + r;
            if (gr < M) {
                float s = scale[gr];
                float2 o;
                unpack2(acc[r], o.x, o.y);
                o.x *= s; o.y *= s;
                *(float2*)&Y[(size_t)gr * N + tx * 2] = o;
            }
        }
    }
}

// ---------------------------------------------------------------------------
// Agg C=128: warp per node, lane owns float4. Batch-8 gathers with NEXT-batch
// index prefetch issued before current accumulation (hides idx latency).
__global__ void agg128_kernel(const int* __restrict__ rowptr, const int* __restrict__ csr_src,
                              const float* __restrict__ h, const float* __restrict__ dinv,
                              const float* __restrict__ bias, float* __restrict__ out, int N) {
    int warp = (blockIdx.x * blockDim.x + threadIdx.x) >> 5;
    int lane = threadIdx.x & 31;
    if (warp >= N) return;
    int j = rowptr[warp], end = rowptr[warp + 1];
    const float4* hv = (const float4*)h;
    float4 acc = make_float4(0.f, 0.f, 0.f, 0.f);

    int s[8];
    bool have = (j + 8 <= end);
    if (have) {
#pragma unroll
        for (int u = 0; u < 8; u++) s[u] = csr_src[j + u];
    }
    while (have) {
        float4 v[8];
#pragma unroll
        for (int u = 0; u < 8; u++) v[u] = hv[(size_t)s[u] * 32 + lane];

        int jn = j + 8;
        bool haveN = (jn + 8 <= end);
        int sn[8];
        if (haveN) {
#pragma unroll
            for (int u = 0; u < 8; u++) sn[u] = csr_src[jn + u];
        }
#pragma unroll
        for (int u = 0; u < 8; u++) {
            acc.x += v[u].x; acc.y += v[u].y; acc.z += v[u].z; acc.w += v[u].w;
        }
#pragma unroll
        for (int u = 0; u < 8; u++) s[u] = sn[u];
        j = jn; have = haveN;
    }
    for (; j < end; j++) {
        int si = csr_src[j];
        float4 a = hv[(size_t)si * 32 + lane];
        acc.x += a.x; acc.y += a.y; acc.z += a.z; acc.w += a.w;
    }
    float dn = dinv[warp];
    float4 bv = ((const float4*)bias)[lane];
    float4 o = make_float4(acc.x * dn + bv.x, acc.y * dn + bv.y,
                           acc.z * dn + bv.z, acc.w * dn + bv.w);
    ((float4*)out)[(size_t)warp * 32 + lane] = o;
}

// Agg C=64: warp per node, lane owns float2. Batch-16 with index prefetch.
__global__ void agg64_kernel(const int* __restrict__ rowptr, const int* __restrict__ csr_src,
                             const float* __restrict__ h, const float* __restrict__ dinv,
                             const float* __restrict__ bias, float* __restrict__ out, int N) {
    int warp = (blockIdx.x * blockDim.x + threadIdx.x) >> 5;
    int lane = threadIdx.x & 31;
    if (warp >= N) return;
    int j = rowptr[warp], end = rowptr[warp + 1];
    const float2* hv = (const float2*)h;
    float2 acc = make_float2(0.f, 0.f);

    int s[16];
    bool have = (j + 16 <= end);
    if (have) {
#pragma unroll
        for (int u = 0; u < 16; u++) s[u] = csr_src[j + u];
    }
    while (have) {
        float2 v[16];
#pragma unroll
        for (int u = 0; u < 16; u++) v[u] = hv[(size_t)s[u] * 32 + lane];

        int jn = j + 16;
        bool haveN = (jn + 16 <= end);
        int sn[16];
        if (haveN) {
#pragma unroll
            for (int u = 0; u < 16; u++) sn[u] = csr_src[jn + u];
        }
#pragma unroll
        for (int u = 0; u < 16; u++) { acc.x += v[u].x; acc.y += v[u].y; }
#pragma unroll
        for (int u = 0; u < 16; u++) s[u] = sn[u];
        j = jn; have = haveN;
    }
    for (; j < end; j++) {
        int si = csr_src[j];
        float2 a = hv[(size_t)si * 32 + lane];
        acc.x += a.x; acc.y += a.y;
    }
    float dn = dinv[warp];
    float2 bv = ((const float2*)bias)[lane];
    float2 o = make_float2(acc.x * dn + bv.x, acc.y * dn + bv.y);
    ((float2*)out)[(size_t)warp * 32 + lane] = o;
}

// ---------------------------------------------------------------------------
extern "C" void kernel_launch(void* const* d_in, const int* in_sizes, int n_in,
                              void* d_out, int out_size) {
    const float* x  = (const float*)d_in[0];
    const int*   ei = (const int*)d_in[1];
    const float* W1 = (const float*)d_in[2];
    const float* b1 = (const float*)d_in[3];
    const float* W2 = (const float*)d_in[4];
    const float* b2 = (const float*)d_in[5];
    float* out = (float*)d_out;

    const int N = in_sizes[0] / IN_DIM;
    const int E = in_sizes[1] / 2;
    const int* src = ei;
    const int* dst = ei + E;

    int *p_degi, *p_rowptr, *p_cursor, *p_csr;
    float *p_dinv, *p_h1, *p_acc1, *p_h2;
    cudaGetSymbolAddress((void**)&p_degi,   g_degi);
    cudaGetSymbolAddress((void**)&p_rowptr, g_rowptr);
    cudaGetSymbolAddress((void**)&p_cursor, g_cursor);
    cudaGetSymbolAddress((void**)&p_csr,    g_csr_src);
    cudaGetSymbolAddress((void**)&p_dinv,   g_dinv);
    cudaGetSymbolAddress((void**)&p_h1,     g_h1);
    cudaGetSymbolAddress((void**)&p_acc1,   g_acc1);
    cudaGetSymbolAddress((void**)&p_h2,     g_h2);

    const int smem1 = (IN_DIM * HID_DIM + 64 * IN_DIM) * 4;   // 96 KB
    const int smem2 = (HID_DIM * OUT_DIM + 64 * HID_DIM) * 4; // 64 KB
    cudaFuncSetAttribute((const void*)gemm_kernel<IN_DIM, HID_DIM, false>,
                         cudaFuncAttributeMaxDynamicSharedMemorySize, smem1);
    cudaFuncSetAttribute((const void*)gemm_kernel<HID_DIM, OUT_DIM, true>,
                         cudaFuncAttributeMaxDynamicSharedMemorySize, smem2);

    // --- CSR build ---
    cudaMemsetAsync(p_degi, 0, (size_t)N * sizeof(int));
    deg_kernel<<<(E + 255) / 256, 256>>>(dst, p_degi, E);
    scan_kernel<<<1, 1024>>>(p_degi, p_rowptr, p_cursor, p_dinv, N, E);
    fill_kernel<<<(E + 255) / 256, 256>>>(src, dst, p_cursor, p_csr, E);

    // --- layer 1 ---
    gemm_kernel<IN_DIM, HID_DIM, false>
        <<<(N + 63) / 64, 256, smem1>>>(x, W1, p_dinv, p_h1, N);
    agg128_kernel<<<(N * 32 + 255) / 256, 256>>>(p_rowptr, p_csr, p_h1, p_dinv, b1, p_acc1, N);

    // --- layer 2 ---
    gemm_kernel<HID_DIM, OUT_DIM, true>
        <<<(N + 63) / 64, 256, smem2>>>(p_acc1, W2, p_dinv, p_h2, N);
    agg64_kernel<<<(N * 32 + 255) / 256, 256>>>(p_rowptr, p_csr, p_h2, p_dinv, b2, out, N);
}